// round 1
// baseline (speedup 1.0000x reference)
#include <cuda_runtime.h>
#include <stdint.h>

// Problem constants (fixed shapes)
#define N_MAX 100000
#define E_MAX 3200000

// ---------------- scratch (static device globals; no allocation) ----------------
__device__ int   g_deg[N_MAX];
__device__ int   g_rowptr[N_MAX + 1];
__device__ int   g_cursor[N_MAX];
__device__ int   g_bsum[256];
__device__ int2  g_cw[E_MAX];            // (src index, weight bits)
__device__ float g_dinv[N_MAX];
__device__ __align__(16) float g_x32[N_MAX * 32];
__device__ __align__(16) float g_hA[N_MAX * 128];
__device__ __align__(16) float g_hB[N_MAX * 128];
__device__ int   g_is64;

// ---------------- init / dtype sniff ----------------
__global__ void k_init(int n) {
    int i = blockIdx.x * blockDim.x + threadIdx.x;
    if (i < n) g_deg[i] = 0;
    if (i == 0) g_is64 = 1;
}

// If edge_index is int64, every odd 32-bit word in the first 2E words is the
// hi half of a non-negative id < 2^31 -> zero. If it's int32, odd words are
// real ids (non-zero with overwhelming probability over 1.6M samples).
__global__ void k_sniff(const unsigned int* __restrict__ w, int E) {
    int stride = gridDim.x * blockDim.x;
    for (int i = blockIdx.x * blockDim.x + threadIdx.x; i < E; i += stride) {
        if (w[2 * i + 1] != 0u) g_is64 = 0;
    }
}

__device__ __forceinline__ int edge_at(const void* ei, int pos, int is64) {
    if (is64) return (int)((const long long*)ei)[pos];
    return ((const int*)ei)[pos];
}

// ---------------- pad x to 32 cols ----------------
__global__ void k_pad(const float* __restrict__ x, int n) {
    int idx = blockIdx.x * blockDim.x + threadIdx.x;
    if (idx >= n * 32) return;
    int i = idx >> 5, f = idx & 31;
    g_x32[idx] = (f < 21) ? x[i * 21 + f] : 0.f;
}

// ---------------- degree histogram ----------------
__global__ void k_deg(const void* __restrict__ ei, int E) {
    int e = blockIdx.x * blockDim.x + threadIdx.x;
    if (e >= E) return;
    int is64 = g_is64;
    int dst = edge_at(ei, E + e, is64);
    atomicAdd(&g_deg[dst], 1);
}

__global__ void k_dinv(int n) {
    int i = blockIdx.x * blockDim.x + threadIdx.x;
    if (i >= n) return;
    g_dinv[i] = rsqrtf((float)(g_deg[i] + 1));   // self-loop included
}

// ---------------- exclusive scan (3 phases) ----------------
__global__ void k_scan1(int n) {
    __shared__ int sh[1024];
    int tid = threadIdx.x;
    int i = blockIdx.x * 1024 + tid;
    int v = (i < n) ? g_deg[i] : 0;
    sh[tid] = v;
    __syncthreads();
    for (int off = 1; off < 1024; off <<= 1) {
        int t = (tid >= off) ? sh[tid - off] : 0;
        __syncthreads();
        sh[tid] += t;
        __syncthreads();
    }
    if (i < n) g_rowptr[i] = sh[tid] - v;   // exclusive
    if (tid == 1023) g_bsum[blockIdx.x] = sh[1023];
}

__global__ void k_scan2(int nb) {
    if (threadIdx.x == 0 && blockIdx.x == 0) {
        int acc = 0;
        for (int b = 0; b < nb; b++) { int t = g_bsum[b]; g_bsum[b] = acc; acc += t; }
    }
}

__global__ void k_scan3(int n, int E) {
    int i = blockIdx.x * 1024 + threadIdx.x;
    if (i < n) {
        int v = g_rowptr[i] + g_bsum[blockIdx.x];
        g_rowptr[i] = v;
        g_cursor[i] = v;
    }
    if (i == 0) g_rowptr[n] = E;
}

// ---------------- CSR scatter (col + edge weight packed) ----------------
__global__ void k_scatter(const void* __restrict__ ei, int E) {
    int e = blockIdx.x * blockDim.x + threadIdx.x;
    if (e >= E) return;
    int is64 = g_is64;
    int src = edge_at(ei, e, is64);
    int dst = edge_at(ei, E + e, is64);
    int pos = atomicAdd(&g_cursor[dst], 1);
    float w = g_dinv[src] * g_dinv[dst];
    g_cw[pos] = make_int2(src, __float_as_int(w));
}

// ---------------- aggregation: warp per node ----------------
// D = 32 floats per row (one 128B line per neighbor)
__global__ void k_agg_d32(const float* __restrict__ h, float* __restrict__ out, int n) {
    int gw = (blockIdx.x * blockDim.x + threadIdx.x) >> 5;
    int lane = threadIdx.x & 31;
    if (gw >= n) return;
    int start = g_rowptr[gw], end = g_rowptr[gw + 1];
    float di = g_dinv[gw];
    float acc = di * di * h[(gw << 5) + lane];
    int k = start;
    for (; k + 4 <= end; k += 4) {
        int2 c0 = g_cw[k], c1 = g_cw[k + 1], c2 = g_cw[k + 2], c3 = g_cw[k + 3];
        float v0 = h[(c0.x << 5) + lane];
        float v1 = h[(c1.x << 5) + lane];
        float v2 = h[(c2.x << 5) + lane];
        float v3 = h[(c3.x << 5) + lane];
        acc += __int_as_float(c0.y) * v0;
        acc += __int_as_float(c1.y) * v1;
        acc += __int_as_float(c2.y) * v2;
        acc += __int_as_float(c3.y) * v3;
    }
    for (; k < end; k++) {
        int2 c = g_cw[k];
        acc += __int_as_float(c.y) * h[(c.x << 5) + lane];
    }
    out[(gw << 5) + lane] = acc;
}

// D = 64 floats per row (lane handles a float2)
__global__ void k_agg_d64(const float* __restrict__ h, float* __restrict__ out, int n) {
    int gw = (blockIdx.x * blockDim.x + threadIdx.x) >> 5;
    int lane = threadIdx.x & 31;
    if (gw >= n) return;
    const float2* __restrict__ h2 = (const float2*)h;
    float2* __restrict__ o2 = (float2*)out;
    int start = g_rowptr[gw], end = g_rowptr[gw + 1];
    float di = g_dinv[gw];
    float sw = di * di;
    float2 hv = h2[(gw << 5) + lane];
    float ax = sw * hv.x, ay = sw * hv.y;
    int k = start;
    for (; k + 4 <= end; k += 4) {
        int2 c0 = g_cw[k], c1 = g_cw[k + 1], c2 = g_cw[k + 2], c3 = g_cw[k + 3];
        float2 v0 = h2[(c0.x << 5) + lane];
        float2 v1 = h2[(c1.x << 5) + lane];
        float2 v2 = h2[(c2.x << 5) + lane];
        float2 v3 = h2[(c3.x << 5) + lane];
        float w0 = __int_as_float(c0.y), w1 = __int_as_float(c1.y);
        float w2 = __int_as_float(c2.y), w3 = __int_as_float(c3.y);
        ax += w0 * v0.x; ay += w0 * v0.y;
        ax += w1 * v1.x; ay += w1 * v1.y;
        ax += w2 * v2.x; ay += w2 * v2.y;
        ax += w3 * v3.x; ay += w3 * v3.y;
    }
    for (; k < end; k++) {
        int2 c = g_cw[k];
        float2 v = h2[(c.x << 5) + lane];
        float w = __int_as_float(c.y);
        ax += w * v.x; ay += w * v.y;
    }
    o2[(gw << 5) + lane] = make_float2(ax, ay);
}

// ---------------- GEMM + optional bias + optional relu ----------------
// blockDim (32,8); block computes 64 rows x 32 cols; thread: 8 rows x 1 col
__global__ void k_gemm(const float* __restrict__ A, int lda,
                       const float* __restrict__ W,
                       const float* __restrict__ bias,
                       float* __restrict__ C, int ldc,
                       int n, int K, int N, int relu) {
    __shared__ float sW[128 * 32];
    int tx = threadIdx.x, ty = threadIdx.y;
    int tid = ty * 32 + tx;
    int colBase = blockIdx.x * 32;
    for (int idx = tid; idx < K * 32; idx += 256) {
        int k = idx >> 5, c = idx & 31;
        int col = colBase + c;
        sW[idx] = (col < N) ? W[k * N + col] : 0.f;
    }
    __syncthreads();

    int rowBase = blockIdx.y * 64 + ty * 8;
    float acc[8] = {0, 0, 0, 0, 0, 0, 0, 0};
    if (rowBase + 7 < n) {
        #pragma unroll 4
        for (int k = 0; k < K; k++) {
            float wv = sW[(k << 5) + tx];
            #pragma unroll
            for (int r = 0; r < 8; r++)
                acc[r] += A[(rowBase + r) * lda + k] * wv;
        }
    } else {
        for (int k = 0; k < K; k++) {
            float wv = sW[(k << 5) + tx];
            #pragma unroll
            for (int r = 0; r < 8; r++) {
                int row = rowBase + r;
                if (row < n) acc[r] += A[row * lda + k] * wv;
            }
        }
    }
    int col = colBase + tx;
    if (col < N) {
        float bv = bias ? bias[col] : 0.f;
        #pragma unroll
        for (int r = 0; r < 8; r++) {
            int row = rowBase + r;
            if (row >= n) break;
            float v = acc[r] + bv;
            if (relu) v = fmaxf(v, 0.f);
            C[row * ldc + col] = v;
        }
    }
}

// ---------------- fused: +b3, relu, MLP head ----------------
__global__ void k_head(const float* __restrict__ a3, const float* __restrict__ b3,
                       const float* __restrict__ Wl1, const float* __restrict__ bl1,
                       const float* __restrict__ Wl2, const float* __restrict__ bl2,
                       float* __restrict__ out, int n) {
    __shared__ float sW1[64 * 20], sb3[64], sb1[20], sW2[20];
    __shared__ float sb2;
    int tid = threadIdx.x;
    for (int i = tid; i < 64 * 20; i += blockDim.x) sW1[i] = Wl1[i];
    if (tid < 64) sb3[tid] = b3[tid];
    if (tid < 20) { sb1[tid] = bl1[tid]; sW2[tid] = Wl2[tid]; }
    if (tid == 0) sb2 = bl2[0];
    __syncthreads();
    int i = blockIdx.x * blockDim.x + tid;
    if (i >= n) return;
    float m[20];
    #pragma unroll
    for (int j = 0; j < 20; j++) m[j] = sb1[j];
    const float* row = a3 + (size_t)i * 64;
    #pragma unroll 4
    for (int f = 0; f < 64; f++) {
        float tf = fmaxf(row[f] + sb3[f], 0.f);
        #pragma unroll
        for (int j = 0; j < 20; j++) m[j] += tf * sW1[f * 20 + j];
    }
    float o = sb2;
    #pragma unroll
    for (int j = 0; j < 20; j++) o += fmaxf(m[j], 0.f) * sW2[j];
    out[i] = o;
}

// ---------------- launch ----------------
extern "C" void kernel_launch(void* const* d_in, const int* in_sizes, int n_in,
                              void* d_out, int out_size) {
    const float* x  = (const float*)d_in[0];
    const void*  ei = d_in[1];
    const float* W1 = (const float*)d_in[2];
    const float* b1 = (const float*)d_in[3];
    const float* W2 = (const float*)d_in[4];
    const float* b2 = (const float*)d_in[5];
    const float* W3 = (const float*)d_in[6];
    const float* b3 = (const float*)d_in[7];
    const float* Wl1 = (const float*)d_in[8];
    const float* bl1 = (const float*)d_in[9];
    const float* Wl2 = (const float*)d_in[10];
    const float* bl2 = (const float*)d_in[11];
    float* out = (float*)d_out;

    int n = in_sizes[0] / 21;
    int E = in_sizes[1] / 2;
    if (n > N_MAX) n = N_MAX;
    if (E > E_MAX) E = E_MAX;

    float *hA, *hB, *x32;
    cudaGetSymbolAddress((void**)&hA, g_hA);
    cudaGetSymbolAddress((void**)&hB, g_hB);
    cudaGetSymbolAddress((void**)&x32, g_x32);

    const int T = 256;
    int nb1024 = (n + 1023) / 1024;

    k_init<<<(n + T - 1) / T, T>>>(n);
    k_sniff<<<1024, T>>>((const unsigned int*)ei, E);
    k_pad<<<(n * 32 + T - 1) / T, T>>>(x, n);
    k_deg<<<(E + T - 1) / T, T>>>(ei, E);
    k_dinv<<<(n + T - 1) / T, T>>>(n);
    k_scan1<<<nb1024, 1024>>>(n);
    k_scan2<<<1, 32>>>(nb1024);
    k_scan3<<<nb1024, 1024>>>(n, E);
    k_scatter<<<(E + T - 1) / T, T>>>(ei, E);

    int aggBlocks = (n + 7) / 8;                 // 8 warps per 256-thread block
    dim3 gThreads(32, 8);

    // layer1: ax = Â x  (D=32 padded), h1 = relu(ax @ W1 + b1)
    k_agg_d32<<<aggBlocks, T>>>(x32, hA, n);
    k_gemm<<<dim3(2, (n + 63) / 64), gThreads>>>(hA, 32, W1, b1, hB, 64, n, 21, 64, 1);

    // layer2: a2 = Â h1 (D=64), h2 = relu(a2 @ W2 + b2)
    k_agg_d64<<<aggBlocks, T>>>(hB, hA, n);
    k_gemm<<<dim3(4, (n + 63) / 64), gThreads>>>(hA, 64, W2, b2, hB, 128, n, 64, 128, 1);

    // layer3: t = h2 @ W3 (no bias), a3 = Â t (D=64); bias+relu fused into head
    k_gemm<<<dim3(2, (n + 63) / 64), gThreads>>>(hB, 128, W3, nullptr, hA, 64, n, 128, 64, 0);
    k_agg_d64<<<aggBlocks, T>>>(hA, hB, n);

    // head: relu(a3 + b3) -> 20 (relu) -> 1
    k_head<<<(n + T - 1) / T, T>>>(hB, b3, Wl1, bl1, Wl2, bl2, out, n);
}

// round 2
// speedup vs baseline: 1.7529x; 1.7529x over previous
#include <cuda_runtime.h>
#include <cuda_fp16.h>
#include <stdint.h>

#define N_MAX 100000
#define E_MAX 3200000

// ---------------- scratch (static device globals; no allocation) ----------------
__device__ int   g_deg[N_MAX];
__device__ int   g_rowptr[N_MAX + 1];
__device__ int   g_cursor[N_MAX];
__device__ int   g_bsum[128];
__device__ int2  g_cw[E_MAX];            // (src index, weight bits fp32)
__device__ float g_dinv[N_MAX];
__device__ __align__(16) __half g_x16[N_MAX * 32];   // padded input, fp16
__device__ __align__(16) __half g_h16[N_MAX * 64];   // h1, later t = h2@W3, fp16
__device__ __align__(16) float  g_f0[N_MAX * 64];    // agg outputs (fp32)
__device__ __align__(16) float  g_f1[N_MAX * 128];   // h2 (fp32)
__device__ int   g_is64;

// ---------------- f32x2 helpers (packed dual-FMA; ptxas never emits these) ------
__device__ __forceinline__ void fma2(unsigned long long& d,
                                     unsigned long long a, unsigned long long b) {
    asm("fma.rn.f32x2 %0, %1, %2, %0;" : "+l"(d) : "l"(a), "l"(b));
}
__device__ __forceinline__ unsigned long long pack2(float x, float y) {
    unsigned long long r;
    asm("mov.b64 %0, {%1,%2};" : "=l"(r) : "f"(x), "f"(y));
    return r;
}
__device__ __forceinline__ float2 unpack2(unsigned long long v) {
    float2 f;
    asm("mov.b64 {%0,%1}, %2;" : "=f"(f.x), "=f"(f.y) : "l"(v));
    return f;
}

// ---------------- init: zero deg, pad+convert x to fp16, is64 flag --------------
__global__ void k_pre(const float* __restrict__ x, int n) {
    int idx = blockIdx.x * blockDim.x + threadIdx.x;
    if (idx == 0) g_is64 = 1;
    if (idx < n) g_deg[idx] = 0;
    if (idx < n * 32) {
        int i = idx >> 5, f = idx & 31;
        g_x16[idx] = __float2half((f < 21) ? x[i * 21 + f] : 0.f);
    }
}

// Sample 8192 edges: int64 -> odd 32-bit words are hi halves (all zero);
// int32 -> odd words are real node ids (nonzero w.h.p. ~1-(1e-5)^8192).
__global__ void k_sniff(const unsigned int* __restrict__ w, int cnt) {
    int i = blockIdx.x * blockDim.x + threadIdx.x;
    if (i < cnt && w[2 * i + 1] != 0u) g_is64 = 0;
}

// 4B lo-word read works for both dtypes (ids are non-negative < 2^31)
__device__ __forceinline__ int edge_ld(const int* __restrict__ ei32, int pos, int is64) {
    return is64 ? ei32[pos << 1] : ei32[pos];
}

// ---------------- degree histogram ----------------
__global__ void k_deg(const int* __restrict__ ei32, int E) {
    int e = blockIdx.x * blockDim.x + threadIdx.x;
    if (e >= E) return;
    int is64 = g_is64;
    int dst = edge_ld(ei32, E + e, is64);
    atomicAdd(&g_deg[dst], 1);
}

// ---------------- exclusive scan (3 phases) + dinv fused ----------------
__global__ void k_scan1(int n) {
    __shared__ int sh[1024];
    int tid = threadIdx.x;
    int i = blockIdx.x * 1024 + tid;
    int v = (i < n) ? g_deg[i] : 0;
    if (i < n) g_dinv[i] = rsqrtf((float)(v + 1));   // self-loop included
    sh[tid] = v;
    __syncthreads();
    for (int off = 1; off < 1024; off <<= 1) {
        int t = (tid >= off) ? sh[tid - off] : 0;
        __syncthreads();
        sh[tid] += t;
        __syncthreads();
    }
    if (i < n) g_rowptr[i] = sh[tid] - v;   // exclusive
    if (tid == 1023) g_bsum[blockIdx.x] = sh[1023];
}

__global__ void k_scan2(int nb) {
    if (threadIdx.x == 0 && blockIdx.x == 0) {
        int acc = 0;
        for (int b = 0; b < nb; b++) { int t = g_bsum[b]; g_bsum[b] = acc; acc += t; }
    }
}

__global__ void k_scan3(int n, int E) {
    int i = blockIdx.x * 1024 + threadIdx.x;
    if (i < n) {
        int v = g_rowptr[i] + g_bsum[blockIdx.x];
        g_rowptr[i] = v;
        g_cursor[i] = v;
    }
    if (i == 0) g_rowptr[n] = E;
}

// ---------------- CSR scatter (src + edge weight packed) ----------------
__global__ void k_scatter(const int* __restrict__ ei32, int E) {
    int e = blockIdx.x * blockDim.x + threadIdx.x;
    if (e >= E) return;
    int is64 = g_is64;
    int src = edge_ld(ei32, e, is64);
    int dst = edge_ld(ei32, E + e, is64);
    int pos = atomicAdd(&g_cursor[dst], 1);
    float w = g_dinv[src] * g_dinv[dst];
    g_cw[pos] = make_int2(src, __float_as_int(w));
}

// ---------------- aggregation: warp per node, fp16 gather, fp32 accumulate -----
// 32 halfs per row (64B per neighbor)
__global__ void k_agg_h32(const __half* __restrict__ h, float* __restrict__ out, int n) {
    int gw = (blockIdx.x * blockDim.x + threadIdx.x) >> 5;
    int lane = threadIdx.x & 31;
    if (gw >= n) return;
    int start = g_rowptr[gw], end = g_rowptr[gw + 1];
    float di = g_dinv[gw];
    float acc = di * di * __half2float(h[(gw << 5) + lane]);
    int k = start;
    for (; k + 4 <= end; k += 4) {
        int2 c0 = g_cw[k], c1 = g_cw[k + 1], c2 = g_cw[k + 2], c3 = g_cw[k + 3];
        float v0 = __half2float(h[(c0.x << 5) + lane]);
        float v1 = __half2float(h[(c1.x << 5) + lane]);
        float v2 = __half2float(h[(c2.x << 5) + lane]);
        float v3 = __half2float(h[(c3.x << 5) + lane]);
        acc += __int_as_float(c0.y) * v0;
        acc += __int_as_float(c1.y) * v1;
        acc += __int_as_float(c2.y) * v2;
        acc += __int_as_float(c3.y) * v3;
    }
    for (; k < end; k++) {
        int2 c = g_cw[k];
        acc += __int_as_float(c.y) * __half2float(h[(c.x << 5) + lane]);
    }
    out[(gw << 5) + lane] = acc;
}

// 64 halfs per row = 32 half2 per row (128B per neighbor); lane owns one half2
__global__ void k_agg_h64(const __half2* __restrict__ h2, float2* __restrict__ o2, int n) {
    int gw = (blockIdx.x * blockDim.x + threadIdx.x) >> 5;
    int lane = threadIdx.x & 31;
    if (gw >= n) return;
    int start = g_rowptr[gw], end = g_rowptr[gw + 1];
    float di = g_dinv[gw];
    float sw = di * di;
    float2 hv = __half22float2(h2[(gw << 5) + lane]);
    float ax = sw * hv.x, ay = sw * hv.y;
    int k = start;
    for (; k + 4 <= end; k += 4) {
        int2 c0 = g_cw[k], c1 = g_cw[k + 1], c2 = g_cw[k + 2], c3 = g_cw[k + 3];
        float2 v0 = __half22float2(h2[(c0.x << 5) + lane]);
        float2 v1 = __half22float2(h2[(c1.x << 5) + lane]);
        float2 v2 = __half22float2(h2[(c2.x << 5) + lane]);
        float2 v3 = __half22float2(h2[(c3.x << 5) + lane]);
        float w0 = __int_as_float(c0.y), w1 = __int_as_float(c1.y);
        float w2 = __int_as_float(c2.y), w3 = __int_as_float(c3.y);
        ax += w0 * v0.x; ay += w0 * v0.y;
        ax += w1 * v1.x; ay += w1 * v1.y;
        ax += w2 * v2.x; ay += w2 * v2.y;
        ax += w3 * v3.x; ay += w3 * v3.y;
    }
    for (; k < end; k++) {
        int2 c = g_cw[k];
        float2 v = __half22float2(h2[(c.x << 5) + lane]);
        float w = __int_as_float(c.y);
        ax += w * v.x; ay += w * v.y;
    }
    o2[(gw << 5) + lane] = make_float2(ax, ay);
}

// ---------------- tiled GEMM with fma.rn.f32x2 ----------------
// BM=64, BN=64, BK=32; 256 threads; micro-tile 4 rows x 4 cols (2 f32x2 pairs).
// A [n, lda] fp32 row-major; W [Kw, N] fp32; out fp32 (Cf) or fp16 (Ch).
__global__ void k_gemm(const float* __restrict__ A, int lda, int K, int Kw,
                       const float* __restrict__ W, int N,
                       const float* __restrict__ bias,
                       float* __restrict__ Cf, __half* __restrict__ Ch,
                       int relu, int n) {
    __shared__ __align__(16) float As[32][68];   // transposed, padded
    __shared__ __align__(16) float Ws[32][64];
    int tid = threadIdx.x;
    int trow = tid >> 4, tcol = tid & 15;
    int rowBase = blockIdx.y << 6;
    int colBase = blockIdx.x << 6;
    int lr = tid >> 3;          // loader row 0..31
    int lf = (tid & 7) << 2;    // loader k offset 0,4,..,28

    unsigned long long acc[4][2];
    #pragma unroll
    for (int r = 0; r < 4; r++) { acc[r][0] = 0ull; acc[r][1] = 0ull; }

    for (int k0 = 0; k0 < K; k0 += 32) {
        #pragma unroll
        for (int hh = 0; hh < 2; hh++) {
            int row = rowBase + lr + hh * 32;
            float4 v = make_float4(0.f, 0.f, 0.f, 0.f);
            if (row < n) v = *(const float4*)(A + (size_t)row * lda + k0 + lf);
            As[lf + 0][lr + hh * 32] = v.x;
            As[lf + 1][lr + hh * 32] = v.y;
            As[lf + 2][lr + hh * 32] = v.z;
            As[lf + 3][lr + hh * 32] = v.w;
        }
        #pragma unroll
        for (int i = 0; i < 2; i++) {
            int lin = tid + (i << 8);
            int kr = lin >> 4, c4 = (lin & 15) << 2;
            float4 wv = make_float4(0.f, 0.f, 0.f, 0.f);
            if (k0 + kr < Kw) wv = *(const float4*)(W + (size_t)(k0 + kr) * N + colBase + c4);
            *(float4*)&Ws[kr][c4] = wv;
        }
        __syncthreads();
        #pragma unroll
        for (int kk = 0; kk < 32; kk++) {
            float4 a4 = *(const float4*)&As[kk][trow << 2];
            ulonglong2 wv = *(const ulonglong2*)&Ws[kk][tcol << 2];
            unsigned long long a0 = pack2(a4.x, a4.x);
            unsigned long long a1 = pack2(a4.y, a4.y);
            unsigned long long a2 = pack2(a4.z, a4.z);
            unsigned long long a3 = pack2(a4.w, a4.w);
            fma2(acc[0][0], a0, wv.x); fma2(acc[0][1], a0, wv.y);
            fma2(acc[1][0], a1, wv.x); fma2(acc[1][1], a1, wv.y);
            fma2(acc[2][0], a2, wv.x); fma2(acc[2][1], a2, wv.y);
            fma2(acc[3][0], a3, wv.x); fma2(acc[3][1], a3, wv.y);
        }
        __syncthreads();
    }

    int col = colBase + (tcol << 2);
    float b0 = 0.f, b1 = 0.f, b2 = 0.f, b3v = 0.f;
    if (bias) { b0 = bias[col]; b1 = bias[col + 1]; b2 = bias[col + 2]; b3v = bias[col + 3]; }
    #pragma unroll
    for (int r = 0; r < 4; r++) {
        int row = rowBase + (trow << 2) + r;
        if (row >= n) break;
        float2 p0 = unpack2(acc[r][0]);
        float2 p1 = unpack2(acc[r][1]);
        float v0 = p0.x + b0, v1 = p0.y + b1, v2 = p1.x + b2, v3 = p1.y + b3v;
        if (relu) {
            v0 = fmaxf(v0, 0.f); v1 = fmaxf(v1, 0.f);
            v2 = fmaxf(v2, 0.f); v3 = fmaxf(v3, 0.f);
        }
        if (Ch) {
            __half2 h0 = __floats2half2_rn(v0, v1);
            __half2 h1 = __floats2half2_rn(v2, v3);
            *(__half2*)(Ch + (size_t)row * N + col) = h0;
            *(__half2*)(Ch + (size_t)row * N + col + 2) = h1;
        } else {
            *(float4*)(Cf + (size_t)row * N + col) = make_float4(v0, v1, v2, v3);
        }
    }
}

// ---------------- fused: +b3, relu, MLP head ----------------
__global__ void k_head(const float* __restrict__ a3, const float* __restrict__ b3,
                       const float* __restrict__ Wl1, const float* __restrict__ bl1,
                       const float* __restrict__ Wl2, const float* __restrict__ bl2,
                       float* __restrict__ out, int n) {
    __shared__ float sW1[64 * 20], sb3[64], sb1[20], sW2[20];
    __shared__ float sb2;
    int tid = threadIdx.x;
    for (int i = tid; i < 64 * 20; i += blockDim.x) sW1[i] = Wl1[i];
    if (tid < 64) sb3[tid] = b3[tid];
    if (tid < 20) { sb1[tid] = bl1[tid]; sW2[tid] = Wl2[tid]; }
    if (tid == 0) sb2 = bl2[0];
    __syncthreads();
    int i = blockIdx.x * blockDim.x + tid;
    if (i >= n) return;
    float m[20];
    #pragma unroll
    for (int j = 0; j < 20; j++) m[j] = sb1[j];
    const float* row = a3 + (size_t)i * 64;
    #pragma unroll 4
    for (int f = 0; f < 64; f++) {
        float tf = fmaxf(row[f] + sb3[f], 0.f);
        #pragma unroll
        for (int j = 0; j < 20; j++) m[j] += tf * sW1[f * 20 + j];
    }
    float o = sb2;
    #pragma unroll
    for (int j = 0; j < 20; j++) o += fmaxf(m[j], 0.f) * sW2[j];
    out[i] = o;
}

// ---------------- launch ----------------
extern "C" void kernel_launch(void* const* d_in, const int* in_sizes, int n_in,
                              void* d_out, int out_size) {
    const float* x   = (const float*)d_in[0];
    const int*   ei  = (const int*)d_in[1];
    const float* W1  = (const float*)d_in[2];
    const float* b1  = (const float*)d_in[3];
    const float* W2  = (const float*)d_in[4];
    const float* b2  = (const float*)d_in[5];
    const float* W3  = (const float*)d_in[6];
    const float* b3  = (const float*)d_in[7];
    const float* Wl1 = (const float*)d_in[8];
    const float* bl1 = (const float*)d_in[9];
    const float* Wl2 = (const float*)d_in[10];
    const float* bl2 = (const float*)d_in[11];
    float* out = (float*)d_out;

    int n = in_sizes[0] / 21;
    int E = in_sizes[1] / 2;
    if (n > N_MAX) n = N_MAX;
    if (E > E_MAX) E = E_MAX;

    __half *x16, *h16;
    float *f0, *f1;
    cudaGetSymbolAddress((void**)&x16, g_x16);
    cudaGetSymbolAddress((void**)&h16, g_h16);
    cudaGetSymbolAddress((void**)&f0, g_f0);
    cudaGetSymbolAddress((void**)&f1, g_f1);

    const int T = 256;
    int nb1024 = (n + 1023) / 1024;
    int aggBlocks = (n + 7) / 8;    // 8 warps (nodes) per 256-thread block
    dim3 gemmT(256);

    k_pre<<<(n * 32 + T - 1) / T, T>>>(x, n);
    k_sniff<<<32, T>>>((const unsigned int*)ei, 8192);
    k_deg<<<(E + T - 1) / T, T>>>(ei, E);
    k_scan1<<<nb1024, 1024>>>(n);
    k_scan2<<<1, 32>>>(nb1024);
    k_scan3<<<nb1024, 1024>>>(n, E);
    k_scatter<<<(E + T - 1) / T, T>>>(ei, E);

    // layer1: a1 = Â x16 (32 cols), h1 = relu(a1 @ W1 + b1) -> fp16
    k_agg_h32<<<aggBlocks, T>>>(x16, f0, n);
    k_gemm<<<dim3(1, (n + 63) / 64), gemmT>>>(f0, 32, 32, 21, W1, 64, b1,
                                              nullptr, h16, 1, n);

    // layer2: a2 = Â h1 (64 cols, fp16 gather), h2 = relu(a2 @ W2 + b2) -> fp32
    k_agg_h64<<<aggBlocks, T>>>((const __half2*)h16, (float2*)f0, n);
    k_gemm<<<dim3(2, (n + 63) / 64), gemmT>>>(f0, 64, 64, 64, W2, 128, b2,
                                              f1, nullptr, 1, n);

    // layer3: t = h2 @ W3 -> fp16 (no bias/relu); a3 = Â t
    k_gemm<<<dim3(1, (n + 63) / 64), gemmT>>>(f1, 128, 128, 128, W3, 64, nullptr,
                                              nullptr, h16, 0, n);
    k_agg_h64<<<aggBlocks, T>>>((const __half2*)h16, (float2*)f0, n);

    // head: relu(a3 + b3) -> 20 (relu) -> 1
    k_head<<<(n + T - 1) / T, T>>>(f0, b3, Wl1, bl1, Wl2, bl2, out, n);
}

// round 3
// speedup vs baseline: 1.8570x; 1.0594x over previous
#include <cuda_runtime.h>
#include <cuda_fp16.h>
#include <mma.h>
#include <stdint.h>

using namespace nvcuda;

#define N_MAX 100000
#define E_MAX 3200000

// ---------------- scratch (static device globals; no allocation) ----------------
__device__ int   g_deg[N_MAX];
__device__ int   g_rowptr[N_MAX + 1];
__device__ int   g_cursor[N_MAX];
__device__ int   g_bsum[128];
__device__ int2  g_cw[E_MAX];            // (src index, weight bits fp32)
__device__ float g_dinv[N_MAX];
__device__ __align__(16) __half g_x16[N_MAX * 32];    // padded input fp16
__device__ __align__(16) __half g_abuf[N_MAX * 64];   // agg outputs / GEMM A; also t
__device__ __align__(16) __half g_hbuf[N_MAX * 128];  // h1, h2, a3
__device__ __align__(16) __half g_w1h[32 * 64];       // W1 padded 21->32 rows
__device__ __align__(16) __half g_w2h[64 * 128];
__device__ __align__(16) __half g_w3h[128 * 64];
__device__ int   g_is64;

// ---------------- pre: is64 sniff (block 0), pad x, zero deg, convert weights ---
__global__ void k_pre(const float* __restrict__ x, const unsigned int* __restrict__ ew,
                      const float* __restrict__ W1, const float* __restrict__ W2,
                      const float* __restrict__ W3, int n) {
    if (blockIdx.x == 0) {
        if (threadIdx.x == 0) g_is64 = 1;
        __syncthreads();
        // sample 8192 edges: int64 -> odd words are zero hi-halves
        bool hit = false;
        #pragma unroll 4
        for (int s = 0; s < 32; s++) {
            int i = threadIdx.x * 32 + s;
            if (ew[2 * i + 1] != 0u) hit = true;
        }
        if (hit) g_is64 = 0;
    }
    int idx = blockIdx.x * blockDim.x + threadIdx.x;
    if (idx < n * 32) {
        int i = idx >> 5, f = idx & 31;
        g_x16[idx] = __float2half((f < 21) ? x[i * 21 + f] : 0.f);
    }
    if (idx < n) g_deg[idx] = 0;
    if (idx < 2048) {                 // W1 pad to 32x64
        int r = idx >> 6, c = idx & 63;
        g_w1h[idx] = __float2half((r < 21) ? W1[r * 64 + c] : 0.f);
    }
    if (idx < 8192) g_w2h[idx] = __float2half(W2[idx]);
    if (idx < 8192) g_w3h[idx] = __float2half(W3[idx]);
}

// ---------------- degree histogram: 4 edges per thread ----------------
__global__ void k_deg(const int* __restrict__ ei32, int E) {
    int e = (blockIdx.x * blockDim.x + threadIdx.x) << 2;
    if (e >= E) return;
    int is64 = g_is64;
    int m = E - e; if (m > 4) m = 4;
    int d[4];
    if (((E & 3) == 0) && m == 4) {
        if (is64) {
            const int4* p = (const int4*)((const long long*)ei32 + E + e);
            int4 q0 = p[0], q1 = p[1];
            d[0] = q0.x; d[1] = q0.z; d[2] = q1.x; d[3] = q1.z;
        } else {
            int4 q = *(const int4*)(ei32 + E + e);
            d[0] = q.x; d[1] = q.y; d[2] = q.z; d[3] = q.w;
        }
        atomicAdd(&g_deg[d[0]], 1); atomicAdd(&g_deg[d[1]], 1);
        atomicAdd(&g_deg[d[2]], 1); atomicAdd(&g_deg[d[3]], 1);
    } else {
        for (int j = 0; j < m; j++) {
            int dd = is64 ? ei32[(E + e + j) << 1] : ei32[E + e + j];
            atomicAdd(&g_deg[dd], 1);
        }
    }
}

// ---------------- exclusive scan (3 phases) + dinv fused ----------------
__global__ void k_scan1(int n) {
    __shared__ int sh[1024];
    int tid = threadIdx.x;
    int i = blockIdx.x * 1024 + tid;
    int v = (i < n) ? g_deg[i] : 0;
    if (i < n) g_dinv[i] = rsqrtf((float)(v + 1));   // self-loop included
    sh[tid] = v;
    __syncthreads();
    for (int off = 1; off < 1024; off <<= 1) {
        int t = (tid >= off) ? sh[tid - off] : 0;
        __syncthreads();
        sh[tid] += t;
        __syncthreads();
    }
    if (i < n) g_rowptr[i] = sh[tid] - v;
    if (tid == 1023) g_bsum[blockIdx.x] = sh[1023];
}

__global__ void k_scan2(int nb) {
    if (threadIdx.x == 0 && blockIdx.x == 0) {
        int acc = 0;
        for (int b = 0; b < nb; b++) { int t = g_bsum[b]; g_bsum[b] = acc; acc += t; }
    }
}

__global__ void k_scan3(int n, int E) {
    int i = blockIdx.x * 1024 + threadIdx.x;
    if (i < n) {
        int v = g_rowptr[i] + g_bsum[blockIdx.x];
        g_rowptr[i] = v;
        g_cursor[i] = v;
    }
    if (i == 0) g_rowptr[n] = E;
}

// ---------------- CSR scatter ----------------
__global__ void k_scatter(const int* __restrict__ ei32, int E) {
    int e = blockIdx.x * blockDim.x + threadIdx.x;
    if (e >= E) return;
    int is64 = g_is64;
    int src = is64 ? ei32[e << 1] : ei32[e];
    int dst = is64 ? ei32[(E + e) << 1] : ei32[E + e];
    int pos = atomicAdd(&g_cursor[dst], 1);
    float w = g_dinv[src] * g_dinv[dst];
    g_cw[pos] = make_int2(src, __float_as_int(w));
}

// ---------------- aggregation: warp per node, fp16 gather, fp32 acc, fp16 out ---
// 32 halfs per row (64B per neighbor)
__global__ void k_agg_h32(const __half* __restrict__ h, __half* __restrict__ out, int n) {
    int gw = (blockIdx.x * blockDim.x + threadIdx.x) >> 5;
    int lane = threadIdx.x & 31;
    if (gw >= n) return;
    int start = g_rowptr[gw], end = g_rowptr[gw + 1];
    float di = g_dinv[gw];
    float acc = di * di * __half2float(h[(gw << 5) + lane]);
    int k = start;
    #pragma unroll 1
    for (; k + 8 <= end; k += 8) {
        int2 c[8];
        #pragma unroll
        for (int j = 0; j < 8; j++) c[j] = g_cw[k + j];
        float v[8];
        #pragma unroll
        for (int j = 0; j < 8; j++) v[j] = __half2float(h[(c[j].x << 5) + lane]);
        #pragma unroll
        for (int j = 0; j < 8; j++) acc += __int_as_float(c[j].y) * v[j];
    }
    for (; k + 2 <= end; k += 2) {
        int2 c0 = g_cw[k], c1 = g_cw[k + 1];
        float v0 = __half2float(h[(c0.x << 5) + lane]);
        float v1 = __half2float(h[(c1.x << 5) + lane]);
        acc += __int_as_float(c0.y) * v0 + __int_as_float(c1.y) * v1;
    }
    for (; k < end; k++) {
        int2 c = g_cw[k];
        acc += __int_as_float(c.y) * __half2float(h[(c.x << 5) + lane]);
    }
    out[(gw << 5) + lane] = __float2half_rn(acc);
}

// 64 halfs per row = 32 half2 per row (128B per neighbor)
__global__ void k_agg_h64(const __half2* __restrict__ h2, __half2* __restrict__ o2, int n) {
    int gw = (blockIdx.x * blockDim.x + threadIdx.x) >> 5;
    int lane = threadIdx.x & 31;
    if (gw >= n) return;
    int start = g_rowptr[gw], end = g_rowptr[gw + 1];
    float di = g_dinv[gw];
    float sw = di * di;
    float2 hv = __half22float2(h2[(gw << 5) + lane]);
    float ax = sw * hv.x, ay = sw * hv.y;
    int k = start;
    #pragma unroll 1
    for (; k + 8 <= end; k += 8) {
        int2 c[8];
        #pragma unroll
        for (int j = 0; j < 8; j++) c[j] = g_cw[k + j];
        float2 v[8];
        #pragma unroll
        for (int j = 0; j < 8; j++) v[j] = __half22float2(h2[(c[j].x << 5) + lane]);
        #pragma unroll
        for (int j = 0; j < 8; j++) {
            float w = __int_as_float(c[j].y);
            ax += w * v[j].x; ay += w * v[j].y;
        }
    }
    for (; k + 2 <= end; k += 2) {
        int2 c0 = g_cw[k], c1 = g_cw[k + 1];
        float2 v0 = __half22float2(h2[(c0.x << 5) + lane]);
        float2 v1 = __half22float2(h2[(c1.x << 5) + lane]);
        float w0 = __int_as_float(c0.y), w1 = __int_as_float(c1.y);
        ax += w0 * v0.x + w1 * v1.x; ay += w0 * v0.y + w1 * v1.y;
    }
    for (; k < end; k++) {
        int2 c = g_cw[k];
        float2 v = __half22float2(h2[(c.x << 5) + lane]);
        float w = __int_as_float(c.y);
        ax += w * v.x; ay += w * v.y;
    }
    o2[(gw << 5) + lane] = __floats2half2_rn(ax, ay);
}

// ---------------- HMMA GEMM: A[n,K]fp16 @ W[K,N]fp16 (+bias, relu) -> fp16 ------
// Block: 64 rows x N cols, 256 threads (8 warps); warp = 32 rows x (N/4) cols.
template<int K, int N, int RELU, int BIAS>
__global__ void k_hgemm(const __half* __restrict__ A, const __half* __restrict__ Wh,
                        const float* __restrict__ bias, __half* __restrict__ C, int n) {
    constexpr int CF = N / 64;                       // column fragments per warp
    constexpr int SZ_AB = (64 * K + K * N) * 2;
    constexpr int SZ_C = 64 * N * 4;
    constexpr int SZ = SZ_AB > SZ_C ? SZ_AB : SZ_C;
    __shared__ __align__(16) char smem[SZ];
    __half* sA = (__half*)smem;
    __half* sB = (__half*)(smem + 64 * K * 2);
    float*  sC = (float*)smem;                       // aliases sA/sB (used after)

    int tid = threadIdx.x;
    int rowBase = blockIdx.x * 64;

    // stage A (guarded, zero-fill) and W, 16B vectors
    constexpr int AV = 64 * K / 8;
    for (int v = tid; v < AV; v += 256) {
        int r = v / (K / 8);
        int c8 = (v % (K / 8)) * 8;
        int4 val = make_int4(0, 0, 0, 0);
        int row = rowBase + r;
        if (row < n) val = *(const int4*)(A + (size_t)row * K + c8);
        *(int4*)(sA + r * K + c8) = val;
    }
    constexpr int BV = K * N / 8;
    for (int v = tid; v < BV; v += 256)
        *(int4*)(sB + v * 8) = *(const int4*)(Wh + v * 8);
    __syncthreads();

    int wid = tid >> 5;
    int wr = wid >> 2;            // 0..1  (row group of 32)
    int wc = wid & 3;             // 0..3  (col group of 16*CF)
    wmma::fragment<wmma::accumulator, 16, 16, 16, float> acc[2][CF];
    #pragma unroll
    for (int i = 0; i < 2; i++)
        #pragma unroll
        for (int j = 0; j < CF; j++)
            wmma::fill_fragment(acc[i][j], 0.f);

    #pragma unroll
    for (int k = 0; k < K; k += 16) {
        wmma::fragment<wmma::matrix_a, 16, 16, 16, __half, wmma::row_major> af[2];
        wmma::fragment<wmma::matrix_b, 16, 16, 16, __half, wmma::row_major> bf[CF];
        #pragma unroll
        for (int i = 0; i < 2; i++)
            wmma::load_matrix_sync(af[i], sA + (wr * 32 + i * 16) * K + k, K);
        #pragma unroll
        for (int j = 0; j < CF; j++)
            wmma::load_matrix_sync(bf[j], sB + k * N + (wc * CF + j) * 16, N);
        #pragma unroll
        for (int i = 0; i < 2; i++)
            #pragma unroll
            for (int j = 0; j < CF; j++)
                wmma::mma_sync(acc[i][j], af[i], bf[j], acc[i][j]);
    }
    __syncthreads();   // sC aliases sA/sB
    #pragma unroll
    for (int i = 0; i < 2; i++)
        #pragma unroll
        for (int j = 0; j < CF; j++)
            wmma::store_matrix_sync(sC + (wr * 32 + i * 16) * N + (wc * CF + j) * 16,
                                    acc[i][j], N, wmma::mem_row_major);
    __syncthreads();

    // epilogue: bias + relu + fp16 convert, coalesced stores
    constexpr int EV = 64 * N / 4;
    for (int v = tid; v < EV; v += 256) {
        int r = v / (N / 4);
        int c4 = (v % (N / 4)) * 4;
        int row = rowBase + r;
        if (row >= n) continue;
        float4 p = *(const float4*)(sC + r * N + c4);
        float v0 = p.x, v1 = p.y, v2 = p.z, v3 = p.w;
        if (BIAS) {
            v0 += bias[c4]; v1 += bias[c4 + 1]; v2 += bias[c4 + 2]; v3 += bias[c4 + 3];
        }
        if (RELU) {
            v0 = fmaxf(v0, 0.f); v1 = fmaxf(v1, 0.f);
            v2 = fmaxf(v2, 0.f); v3 = fmaxf(v3, 0.f);
        }
        __half2 h0 = __floats2half2_rn(v0, v1);
        __half2 h1 = __floats2half2_rn(v2, v3);
        *(int2*)(C + (size_t)row * N + c4) =
            make_int2(*(int*)&h0, *(int*)&h1);
    }
}

// ---------------- fused: +b3, relu, MLP head (fp16 input) ----------------
__global__ void k_head(const __half2* __restrict__ a3, const float* __restrict__ b3,
                       const float* __restrict__ Wl1, const float* __restrict__ bl1,
                       const float* __restrict__ Wl2, const float* __restrict__ bl2,
                       float* __restrict__ out, int n) {
    __shared__ float sW1[64 * 20], sb3[64], sb1[20], sW2[20];
    __shared__ float sb2;
    int tid = threadIdx.x;
    for (int i = tid; i < 64 * 20; i += blockDim.x) sW1[i] = Wl1[i];
    if (tid < 64) sb3[tid] = b3[tid];
    if (tid < 20) { sb1[tid] = bl1[tid]; sW2[tid] = Wl2[tid]; }
    if (tid == 0) sb2 = bl2[0];
    __syncthreads();
    int i = blockIdx.x * blockDim.x + tid;
    if (i >= n) return;
    float m[20];
    #pragma unroll
    for (int j = 0; j < 20; j++) m[j] = sb1[j];
    const __half2* row = a3 + (size_t)i * 32;
    #pragma unroll 4
    for (int f2 = 0; f2 < 32; f2++) {
        float2 tv = __half22float2(row[f2]);
        float t0 = fmaxf(tv.x + sb3[2 * f2], 0.f);
        float t1 = fmaxf(tv.y + sb3[2 * f2 + 1], 0.f);
        #pragma unroll
        for (int j = 0; j < 20; j++)
            m[j] += t0 * sW1[(2 * f2) * 20 + j] + t1 * sW1[(2 * f2 + 1) * 20 + j];
    }
    float o = sb2;
    #pragma unroll
    for (int j = 0; j < 20; j++) o += fmaxf(m[j], 0.f) * sW2[j];
    out[i] = o;
}

// ---------------- launch ----------------
extern "C" void kernel_launch(void* const* d_in, const int* in_sizes, int n_in,
                              void* d_out, int out_size) {
    const float* x   = (const float*)d_in[0];
    const int*   ei  = (const int*)d_in[1];
    const float* W1  = (const float*)d_in[2];
    const float* b1  = (const float*)d_in[3];
    const float* W2  = (const float*)d_in[4];
    const float* b2  = (const float*)d_in[5];
    const float* W3  = (const float*)d_in[6];
    const float* b3  = (const float*)d_in[7];
    const float* Wl1 = (const float*)d_in[8];
    const float* bl1 = (const float*)d_in[9];
    const float* Wl2 = (const float*)d_in[10];
    const float* bl2 = (const float*)d_in[11];
    float* out = (float*)d_out;

    int n = in_sizes[0] / 21;
    int E = in_sizes[1] / 2;
    if (n > N_MAX) n = N_MAX;
    if (E > E_MAX) E = E_MAX;

    __half *x16, *abuf, *hbuf, *w1h, *w2h, *w3h;
    cudaGetSymbolAddress((void**)&x16, g_x16);
    cudaGetSymbolAddress((void**)&abuf, g_abuf);
    cudaGetSymbolAddress((void**)&hbuf, g_hbuf);
    cudaGetSymbolAddress((void**)&w1h, g_w1h);
    cudaGetSymbolAddress((void**)&w2h, g_w2h);
    cudaGetSymbolAddress((void**)&w3h, g_w3h);

    const int T = 256;
    int nb1024 = (n + 1023) / 1024;
    int aggBlocks = (n + 7) / 8;
    int gemmBlocks = (n + 63) / 64;

    k_pre<<<(n * 32 + T - 1) / T, T>>>(x, (const unsigned int*)ei, W1, W2, W3, n);
    k_deg<<<((E + 3) / 4 + T - 1) / T, T>>>(ei, E);
    k_scan1<<<nb1024, 1024>>>(n);
    k_scan2<<<1, 32>>>(nb1024);
    k_scan3<<<nb1024, 1024>>>(n, E);
    k_scatter<<<(E + T - 1) / T, T>>>(ei, E);

    // layer1: a1 = Â x16 (32), h1 = relu(a1 @ W1 + b1) -> hbuf[n,64]
    k_agg_h32<<<aggBlocks, T>>>(x16, abuf, n);
    k_hgemm<32, 64, 1, 1><<<gemmBlocks, 256>>>(abuf, w1h, b1, hbuf, n);

    // layer2: a2 = Â h1 (64), h2 = relu(a2 @ W2 + b2) -> hbuf[n,128]
    k_agg_h64<<<aggBlocks, T>>>((const __half2*)hbuf, (__half2*)abuf, n);
    k_hgemm<64, 128, 1, 1><<<gemmBlocks, 256>>>(abuf, w2h, b2, hbuf, n);

    // layer3: t = h2 @ W3 -> abuf[n,64]; a3 = Â t -> hbuf[n,64]
    k_hgemm<128, 64, 0, 0><<<gemmBlocks, 256>>>(hbuf, w3h, nullptr, abuf, n);
    k_agg_h64<<<aggBlocks, T>>>((const __half2*)abuf, (__half2*)hbuf, n);

    // head: relu(a3 + b3) -> 20 (relu) -> 1
    k_head<<<(n + T - 1) / T, T>>>((const __half2*)hbuf, b3, Wl1, bl1, Wl2, bl2, out, n);
}

// round 4
// speedup vs baseline: 1.8999x; 1.0231x over previous
#include <cuda_runtime.h>
#include <cuda_fp16.h>
#include <mma.h>
#include <stdint.h>

using namespace nvcuda;

#define N_MAX 100000
#define E_MAX 3200000

// ---------------- scratch (static device globals; no allocation) ----------------
__device__ int   g_deg[N_MAX];
__device__ int   g_rowptr[N_MAX + 1];
__device__ int   g_cursor[N_MAX];
__device__ int   g_bsum[128];
__device__ int2  g_cw[E_MAX];            // (src index, weight bits fp32)
__device__ float g_dinv[N_MAX];
__device__ __align__(16) __half g_x16[N_MAX * 32];    // padded input fp16
__device__ __align__(16) __half g_abuf[N_MAX * 64];   // agg outputs / GEMM A; also t
__device__ __align__(16) __half g_hbuf[N_MAX * 128];  // h1, h2, a3
__device__ __align__(16) __half g_w1h[32 * 64];       // W1 padded 21->32 rows
__device__ __align__(16) __half g_w2h[64 * 128];
__device__ __align__(16) __half g_w3h[128 * 64];
__device__ int   g_is64;

// ---------------- pre: is64 sniff (block 0), pad x, zero deg, convert weights ---
__global__ void k_pre(const float* __restrict__ x, const unsigned int* __restrict__ ew,
                      const float* __restrict__ W1, const float* __restrict__ W2,
                      const float* __restrict__ W3, int n) {
    if (blockIdx.x == 0) {
        if (threadIdx.x == 0) g_is64 = 1;
        __syncthreads();
        bool hit = false;
        #pragma unroll 4
        for (int s = 0; s < 32; s++) {
            int i = threadIdx.x * 32 + s;
            if (ew[2 * i + 1] != 0u) hit = true;
        }
        if (hit) g_is64 = 0;
    }
    int idx = blockIdx.x * blockDim.x + threadIdx.x;
    if (idx < n * 32) {
        int i = idx >> 5, f = idx & 31;
        g_x16[idx] = __float2half((f < 21) ? x[i * 21 + f] : 0.f);
    }
    if (idx < n) g_deg[idx] = 0;
    if (idx < 2048) {                 // W1 pad to 32x64
        int r = idx >> 6, c = idx & 63;
        g_w1h[idx] = __float2half((r < 21) ? W1[r * 64 + c] : 0.f);
    }
    if (idx < 8192) g_w2h[idx] = __float2half(W2[idx]);
    if (idx < 8192) g_w3h[idx] = __float2half(W3[idx]);
}

// ---------------- degree histogram: 4 edges per thread ----------------
__global__ void k_deg(const int* __restrict__ ei32, int E) {
    int e = (blockIdx.x * blockDim.x + threadIdx.x) << 2;
    if (e >= E) return;
    int is64 = g_is64;
    int m = E - e; if (m > 4) m = 4;
    if (((E & 3) == 0) && m == 4) {
        int d[4];
        if (is64) {
            const int4* p = (const int4*)((const long long*)ei32 + E + e);
            int4 q0 = p[0], q1 = p[1];
            d[0] = q0.x; d[1] = q0.z; d[2] = q1.x; d[3] = q1.z;
        } else {
            int4 q = *(const int4*)(ei32 + E + e);
            d[0] = q.x; d[1] = q.y; d[2] = q.z; d[3] = q.w;
        }
        atomicAdd(&g_deg[d[0]], 1); atomicAdd(&g_deg[d[1]], 1);
        atomicAdd(&g_deg[d[2]], 1); atomicAdd(&g_deg[d[3]], 1);
    } else {
        for (int j = 0; j < m; j++) {
            int dd = is64 ? ei32[(E + e + j) << 1] : ei32[E + e + j];
            atomicAdd(&g_deg[dd], 1);
        }
    }
}

// ---------------- scan phase 1: warp-shuffle block scan + dinv -------------------
__global__ void k_scan1(int n) {
    __shared__ int wsum[32];
    int tid = threadIdx.x;
    int i = blockIdx.x * 1024 + tid;
    int v = (i < n) ? g_deg[i] : 0;
    if (i < n) g_dinv[i] = rsqrtf((float)(v + 1));   // self-loop included
    int lane = tid & 31, wid = tid >> 5;
    int inc = v;
    #pragma unroll
    for (int off = 1; off < 32; off <<= 1) {
        int t = __shfl_up_sync(0xffffffffu, inc, off);
        if (lane >= off) inc += t;
    }
    if (lane == 31) wsum[wid] = inc;
    __syncthreads();
    if (wid == 0) {
        int s = wsum[lane];
        #pragma unroll
        for (int off = 1; off < 32; off <<= 1) {
            int t = __shfl_up_sync(0xffffffffu, s, off);
            if (lane >= off) s += t;
        }
        wsum[lane] = s;
    }
    __syncthreads();
    int base = (wid > 0) ? wsum[wid - 1] : 0;
    if (i < n) g_rowptr[i] = base + inc - v;          // exclusive
    if (tid == 1023) g_bsum[blockIdx.x] = wsum[31];
}

// ---------------- scan phase 2: parallel over <=128 block sums -------------------
__global__ void k_scan2(int nb) {
    __shared__ int ws[4];
    int tid = threadIdx.x, lane = tid & 31, wid = tid >> 5;
    int v = (tid < nb) ? g_bsum[tid] : 0;
    int inc = v;
    #pragma unroll
    for (int off = 1; off < 32; off <<= 1) {
        int t = __shfl_up_sync(0xffffffffu, inc, off);
        if (lane >= off) inc += t;
    }
    if (lane == 31) ws[wid] = inc;
    __syncthreads();
    if (tid == 0) {
        int a = 0;
        #pragma unroll
        for (int w = 0; w < 4; w++) { int t = ws[w]; ws[w] = a; a += t; }
    }
    __syncthreads();
    if (tid < nb) g_bsum[tid] = ws[wid] + inc - v;    // exclusive block offsets
}

__global__ void k_scan3(int n, int E) {
    int i = blockIdx.x * 1024 + threadIdx.x;
    if (i < n) {
        int v = g_rowptr[i] + g_bsum[blockIdx.x >> 0 ? blockIdx.x : 0];
        v = g_rowptr[i] + g_bsum[blockIdx.x];
        g_rowptr[i] = v;
        g_cursor[i] = v;
    }
    if (i == 0) g_rowptr[n] = E;
}

// ---------------- CSR scatter: 4 edges per thread, vectorized loads --------------
__global__ void k_scatter(const int* __restrict__ ei32, int E) {
    int e = (blockIdx.x * blockDim.x + threadIdx.x) << 2;
    if (e >= E) return;
    int is64 = g_is64;
    int m = E - e; if (m > 4) m = 4;
    if (((E & 3) == 0) && m == 4) {
        int s[4], d[4];
        if (is64) {
            const int4* ps = (const int4*)((const long long*)ei32 + e);
            int4 a0 = ps[0], a1 = ps[1];
            s[0] = a0.x; s[1] = a0.z; s[2] = a1.x; s[3] = a1.z;
            const int4* pd = (const int4*)((const long long*)ei32 + E + e);
            int4 b0 = pd[0], b1 = pd[1];
            d[0] = b0.x; d[1] = b0.z; d[2] = b1.x; d[3] = b1.z;
        } else {
            int4 a = *(const int4*)(ei32 + e);
            s[0] = a.x; s[1] = a.y; s[2] = a.z; s[3] = a.w;
            int4 b = *(const int4*)(ei32 + E + e);
            d[0] = b.x; d[1] = b.y; d[2] = b.z; d[3] = b.w;
        }
        #pragma unroll
        for (int j = 0; j < 4; j++) {
            int pos = atomicAdd(&g_cursor[d[j]], 1);
            float w = g_dinv[s[j]] * g_dinv[d[j]];
            g_cw[pos] = make_int2(s[j], __float_as_int(w));
        }
    } else {
        for (int j = 0; j < m; j++) {
            int src = is64 ? ei32[(e + j) << 1] : ei32[e + j];
            int dst = is64 ? ei32[(E + e + j) << 1] : ei32[E + e + j];
            int pos = atomicAdd(&g_cursor[dst], 1);
            float w = g_dinv[src] * g_dinv[dst];
            g_cw[pos] = make_int2(src, __float_as_int(w));
        }
    }
}

// ---------------- aggregation: warp per node, smem-staged edge list --------------
// 32 halfs per row (64B per neighbor)
__global__ void k_agg_h32(const __half* __restrict__ h, __half* __restrict__ out, int n) {
    __shared__ int2 scw[8][32];
    int w = threadIdx.x >> 5, lane = threadIdx.x & 31;
    int gw = blockIdx.x * 8 + w;
    if (gw >= n) return;
    int start = g_rowptr[gw], end = g_rowptr[gw + 1];
    float di = g_dinv[gw];
    float acc = di * di * __half2float(h[(gw << 5) + lane]);
    for (int k = start; k < end; k += 32) {
        int cnt = end - k; if (cnt > 32) cnt = 32;
        if (lane < cnt) scw[w][lane] = g_cw[k + lane];
        __syncwarp();
        int j = 0;
        for (; j + 8 <= cnt; j += 8) {
            int2 c[8];
            #pragma unroll
            for (int u = 0; u < 8; u++) c[u] = scw[w][j + u];
            float v[8];
            #pragma unroll
            for (int u = 0; u < 8; u++) v[u] = __half2float(h[(c[u].x << 5) + lane]);
            #pragma unroll
            for (int u = 0; u < 8; u++) acc += __int_as_float(c[u].y) * v[u];
        }
        for (; j < cnt; j++) {
            int2 c = scw[w][j];
            acc += __int_as_float(c.y) * __half2float(h[(c.x << 5) + lane]);
        }
        __syncwarp();
    }
    out[(gw << 5) + lane] = __float2half_rn(acc);
}

// 64 halfs per row = 32 half2 per row (128B per neighbor)
__global__ void k_agg_h64(const __half2* __restrict__ h2, __half2* __restrict__ o2, int n) {
    __shared__ int2 scw[8][32];
    int w = threadIdx.x >> 5, lane = threadIdx.x & 31;
    int gw = blockIdx.x * 8 + w;
    if (gw >= n) return;
    int start = g_rowptr[gw], end = g_rowptr[gw + 1];
    float di = g_dinv[gw];
    float sw = di * di;
    float2 hv = __half22float2(h2[(gw << 5) + lane]);
    float ax = sw * hv.x, ay = sw * hv.y;
    for (int k = start; k < end; k += 32) {
        int cnt = end - k; if (cnt > 32) cnt = 32;
        if (lane < cnt) scw[w][lane] = g_cw[k + lane];
        __syncwarp();
        int j = 0;
        for (; j + 8 <= cnt; j += 8) {
            int2 c[8];
            #pragma unroll
            for (int u = 0; u < 8; u++) c[u] = scw[w][j + u];
            float2 v[8];
            #pragma unroll
            for (int u = 0; u < 8; u++) v[u] = __half22float2(h2[(c[u].x << 5) + lane]);
            #pragma unroll
            for (int u = 0; u < 8; u++) {
                float wt = __int_as_float(c[u].y);
                ax += wt * v[u].x; ay += wt * v[u].y;
            }
        }
        for (; j < cnt; j++) {
            int2 c = scw[w][j];
            float2 v = __half22float2(h2[(c.x << 5) + lane]);
            float wt = __int_as_float(c.y);
            ax += wt * v.x; ay += wt * v.y;
        }
        __syncwarp();
    }
    o2[(gw << 5) + lane] = __floats2half2_rn(ax, ay);
}

// ---------------- HMMA GEMM: A[n,K]fp16 @ W[K,N]fp16 (+bias, relu) -> fp16 ------
template<int K, int N, int RELU, int BIAS>
__global__ void k_hgemm(const __half* __restrict__ A, const __half* __restrict__ Wh,
                        const float* __restrict__ bias, __half* __restrict__ C, int n) {
    constexpr int CF = N / 64;
    constexpr int SZ_AB = (64 * K + K * N) * 2;
    constexpr int SZ_C = 64 * N * 4;
    constexpr int SZ = SZ_AB > SZ_C ? SZ_AB : SZ_C;
    __shared__ __align__(16) char smem[SZ];
    __half* sA = (__half*)smem;
    __half* sB = (__half*)(smem + 64 * K * 2);
    float*  sC = (float*)smem;

    int tid = threadIdx.x;
    int rowBase = blockIdx.x * 64;

    constexpr int AV = 64 * K / 8;
    for (int v = tid; v < AV; v += 256) {
        int r = v / (K / 8);
        int c8 = (v % (K / 8)) * 8;
        int4 val = make_int4(0, 0, 0, 0);
        int row = rowBase + r;
        if (row < n) val = *(const int4*)(A + (size_t)row * K + c8);
        *(int4*)(sA + r * K + c8) = val;
    }
    constexpr int BV = K * N / 8;
    for (int v = tid; v < BV; v += 256)
        *(int4*)(sB + v * 8) = *(const int4*)(Wh + v * 8);
    __syncthreads();

    int wid = tid >> 5;
    int wr = wid >> 2, wc = wid & 3;
    wmma::fragment<wmma::accumulator, 16, 16, 16, float> acc[2][CF];
    #pragma unroll
    for (int i = 0; i < 2; i++)
        #pragma unroll
        for (int j = 0; j < CF; j++)
            wmma::fill_fragment(acc[i][j], 0.f);

    #pragma unroll
    for (int k = 0; k < K; k += 16) {
        wmma::fragment<wmma::matrix_a, 16, 16, 16, __half, wmma::row_major> af[2];
        wmma::fragment<wmma::matrix_b, 16, 16, 16, __half, wmma::row_major> bf[CF];
        #pragma unroll
        for (int i = 0; i < 2; i++)
            wmma::load_matrix_sync(af[i], sA + (wr * 32 + i * 16) * K + k, K);
        #pragma unroll
        for (int j = 0; j < CF; j++)
            wmma::load_matrix_sync(bf[j], sB + k * N + (wc * CF + j) * 16, N);
        #pragma unroll
        for (int i = 0; i < 2; i++)
            #pragma unroll
            for (int j = 0; j < CF; j++)
                wmma::mma_sync(acc[i][j], af[i], bf[j], acc[i][j]);
    }
    __syncthreads();
    #pragma unroll
    for (int i = 0; i < 2; i++)
        #pragma unroll
        for (int j = 0; j < CF; j++)
            wmma::store_matrix_sync(sC + (wr * 32 + i * 16) * N + (wc * CF + j) * 16,
                                    acc[i][j], N, wmma::mem_row_major);
    __syncthreads();

    constexpr int EV = 64 * N / 4;
    for (int v = tid; v < EV; v += 256) {
        int r = v / (N / 4);
        int c4 = (v % (N / 4)) * 4;
        int row = rowBase + r;
        if (row >= n) continue;
        float4 p = *(const float4*)(sC + r * N + c4);
        float v0 = p.x, v1 = p.y, v2 = p.z, v3 = p.w;
        if (BIAS) {
            v0 += bias[c4]; v1 += bias[c4 + 1]; v2 += bias[c4 + 2]; v3 += bias[c4 + 3];
        }
        if (RELU) {
            v0 = fmaxf(v0, 0.f); v1 = fmaxf(v1, 0.f);
            v2 = fmaxf(v2, 0.f); v3 = fmaxf(v3, 0.f);
        }
        __half2 h0 = __floats2half2_rn(v0, v1);
        __half2 h1 = __floats2half2_rn(v2, v3);
        *(int2*)(C + (size_t)row * N + c4) = make_int2(*(int*)&h0, *(int*)&h1);
    }
}

// ---------------- fused: +b3, relu, MLP head (fp16 input) ----------------
__global__ void k_head(const __half2* __restrict__ a3, const float* __restrict__ b3,
                       const float* __restrict__ Wl1, const float* __restrict__ bl1,
                       const float* __restrict__ Wl2, const float* __restrict__ bl2,
                       float* __restrict__ out, int n) {
    __shared__ float sW1[64 * 20], sb3[64], sb1[20], sW2[20];
    __shared__ float sb2;
    int tid = threadIdx.x;
    for (int i = tid; i < 64 * 20; i += blockDim.x) sW1[i] = Wl1[i];
    if (tid < 64) sb3[tid] = b3[tid];
    if (tid < 20) { sb1[tid] = bl1[tid]; sW2[tid] = Wl2[tid]; }
    if (tid == 0) sb2 = bl2[0];
    __syncthreads();
    int i = blockIdx.x * blockDim.x + tid;
    if (i >= n) return;
    float m[20];
    #pragma unroll
    for (int j = 0; j < 20; j++) m[j] = sb1[j];
    const __half2* row = a3 + (size_t)i * 32;
    #pragma unroll 4
    for (int f2 = 0; f2 < 32; f2++) {
        float2 tv = __half22float2(row[f2]);
        float t0 = fmaxf(tv.x + sb3[2 * f2], 0.f);
        float t1 = fmaxf(tv.y + sb3[2 * f2 + 1], 0.f);
        #pragma unroll
        for (int j = 0; j < 20; j++)
            m[j] += t0 * sW1[(2 * f2) * 20 + j] + t1 * sW1[(2 * f2 + 1) * 20 + j];
    }
    float o = sb2;
    #pragma unroll
    for (int j = 0; j < 20; j++) o += fmaxf(m[j], 0.f) * sW2[j];
    out[i] = o;
}

// ---------------- launch ----------------
extern "C" void kernel_launch(void* const* d_in, const int* in_sizes, int n_in,
                              void* d_out, int out_size) {
    const float* x   = (const float*)d_in[0];
    const int*   ei  = (const int*)d_in[1];
    const float* W1  = (const float*)d_in[2];
    const float* b1  = (const float*)d_in[3];
    const float* W2  = (const float*)d_in[4];
    const float* b2  = (const float*)d_in[5];
    const float* W3  = (const float*)d_in[6];
    const float* b3  = (const float*)d_in[7];
    const float* Wl1 = (const float*)d_in[8];
    const float* bl1 = (const float*)d_in[9];
    const float* Wl2 = (const float*)d_in[10];
    const float* bl2 = (const float*)d_in[11];
    float* out = (float*)d_out;

    int n = in_sizes[0] / 21;
    int E = in_sizes[1] / 2;
    if (n > N_MAX) n = N_MAX;
    if (E > E_MAX) E = E_MAX;

    __half *x16, *abuf, *hbuf, *w1h, *w2h, *w3h;
    cudaGetSymbolAddress((void**)&x16, g_x16);
    cudaGetSymbolAddress((void**)&abuf, g_abuf);
    cudaGetSymbolAddress((void**)&hbuf, g_hbuf);
    cudaGetSymbolAddress((void**)&w1h, g_w1h);
    cudaGetSymbolAddress((void**)&w2h, g_w2h);
    cudaGetSymbolAddress((void**)&w3h, g_w3h);

    const int T = 256;
    int nb1024 = (n + 1023) / 1024;
    int aggBlocks = (n + 7) / 8;
    int gemmBlocks = (n + 63) / 64;

    k_pre<<<(n * 32 + T - 1) / T, T>>>(x, (const unsigned int*)ei, W1, W2, W3, n);
    k_deg<<<((E + 3) / 4 + T - 1) / T, T>>>(ei, E);
    k_scan1<<<nb1024, 1024>>>(n);
    k_scan2<<<1, 128>>>(nb1024);
    k_scan3<<<nb1024, 1024>>>(n, E);
    k_scatter<<<((E + 3) / 4 + T - 1) / T, T>>>(ei, E);

    // layer1: a1 = Â x16 (32), h1 = relu(a1 @ W1 + b1) -> hbuf[n,64]
    k_agg_h32<<<aggBlocks, T>>>(x16, abuf, n);
    k_hgemm<32, 64, 1, 1><<<gemmBlocks, 256>>>(abuf, w1h, b1, hbuf, n);

    // layer2: a2 = Â h1 (64), h2 = relu(a2 @ W2 + b2) -> hbuf[n,128]
    k_agg_h64<<<aggBlocks, T>>>((const __half2*)hbuf, (__half2*)abuf, n);
    k_hgemm<64, 128, 1, 1><<<gemmBlocks, 256>>>(abuf, w2h, b2, hbuf, n);

    // layer3: t = h2 @ W3 -> abuf[n,64]; a3 = Â t -> hbuf[n,64]
    k_hgemm<128, 64, 0, 0><<<gemmBlocks, 256>>>(hbuf, w3h, nullptr, abuf, n);
    k_agg_h64<<<aggBlocks, T>>>((const __half2*)abuf, (__half2*)hbuf, n);

    // head: relu(a3 + b3) -> 20 (relu) -> 1
    k_head<<<(n + T - 1) / T, T>>>((const __half2*)hbuf, b3, Wl1, bl1, Wl2, bl2, out, n);
}